// round 14
// baseline (speedup 1.0000x reference)
#include <cuda_runtime.h>
#include <cstdint>

#define B_ 64
#define T_ 2048
#define I_ 512
#define H_ 1024
#define MTOT (B_ * T_)
#define BSTRIDE ((size_t)T_ * H_)   // stride between batch rows in out
#define NBLK 128                    // persistent grid: 16 n-tiles x 8 k-slabs

// Scratch: Uw transposed to [k][n] (R4-validated).
__device__ float g_UwT[H_ * H_];
__device__ unsigned g_bar;          // grid-barrier arrival counter

// ---------------------------------------------------------------------------
// packed-fp32 helpers (sm_103a FFMA2 via PTX fma.rn.f32x2; exact IEEE RN
// per lane -> identical numerics to scalar FFMA in the same order)
// ---------------------------------------------------------------------------
__device__ __forceinline__ unsigned long long dup2(float x) {
    unsigned long long r; unsigned u = __float_as_uint(x);
    asm("mov.b64 %0, {%1, %2};" : "=l"(r) : "r"(u), "r"(u));
    return r;
}
__device__ __forceinline__ void fma2(unsigned long long& d,
                                     unsigned long long a, unsigned long long b) {
    asm("fma.rn.f32x2 %0, %1, %2, %0;" : "+l"(d) : "l"(a), "l"(b));
}
__device__ __forceinline__ float2 unpk(unsigned long long v) {
    unsigned lo, hi;
    asm("mov.b64 {%0, %1}, %2;" : "=r"(lo), "=r"(hi) : "l"(v));
    return make_float2(__uint_as_float(lo), __uint_as_float(hi));
}

// ---------------------------------------------------------------------------
// Transpose Uw[n][k] -> g_UwT[k][n]; also reset the grid barrier. (R4-validated)
// ---------------------------------------------------------------------------
__global__ __launch_bounds__(256) void uw_transpose_kernel(const float* __restrict__ Uw) {
    if (blockIdx.x == 0 && blockIdx.y == 0 && threadIdx.x == 0) g_bar = 0u;
    __shared__ float tile[32][33];
    const int bx = blockIdx.x * 32;
    const int by = blockIdx.y * 32;
    const int tx = threadIdx.x & 31;
    const int tw = threadIdx.x >> 5;
#pragma unroll
    for (int r = 0; r < 32; r += 8)
        tile[tw + r][tx] = Uw[(size_t)(by + tw + r) * H_ + bx + tx];
    __syncthreads();
#pragma unroll
    for (int r = 0; r < 32; r += 8)
        g_UwT[(size_t)(bx + tw + r) * H_ + by + tx] = tile[tx][tw + r];
}

// ---------------------------------------------------------------------------
// Projection (fp32 FFMA2) — R12-validated. out = x@W^T + Ub + b.
// ---------------------------------------------------------------------------
__global__ __launch_bounds__(256) void proj_kernel(
    const float* __restrict__ x, const float* __restrict__ W,
    const float* __restrict__ Ub, const float* __restrict__ bvec,
    float* __restrict__ out)
{
    __shared__ float As[16][128];
    __shared__ float Bs[16][128];
    const int tid = threadIdx.x;
    const int m0 = blockIdx.y * 128;
    const int n0 = blockIdx.x * 128;
    const int ty = tid >> 4;   // 0..15
    const int tx = tid & 15;   // 0..15

    unsigned long long acc[8][4];
#pragma unroll
    for (int i = 0; i < 8; i++)
#pragma unroll
        for (int j = 0; j < 4; j++) acc[i][j] = 0ull;

    for (int kb = 0; kb < I_; kb += 16) {
#pragma unroll
        for (int l = 0; l < 2; l++) {
            int idx = tid + l * 256;
            int row = idx >> 2;
            int c4  = (idx & 3) << 2;
            float4 av = *(const float4*)(x + (size_t)(m0 + row) * I_ + kb + c4);
            As[c4 + 0][row] = av.x; As[c4 + 1][row] = av.y;
            As[c4 + 2][row] = av.z; As[c4 + 3][row] = av.w;
            float4 wv = *(const float4*)(W + (size_t)(n0 + row) * I_ + kb + c4);
            Bs[c4 + 0][row] = wv.x; Bs[c4 + 1][row] = wv.y;
            Bs[c4 + 2][row] = wv.z; Bs[c4 + 3][row] = wv.w;
        }
        __syncthreads();
#pragma unroll
        for (int k = 0; k < 16; k++) {
            float4 a0 = *(const float4*)&As[k][ty * 8];
            float4 a1 = *(const float4*)&As[k][ty * 8 + 4];
            ulonglong2 b01 = *(const ulonglong2*)&Bs[k][tx * 8];
            ulonglong2 b23 = *(const ulonglong2*)&Bs[k][tx * 8 + 4];
            unsigned long long ad[8];
            ad[0] = dup2(a0.x); ad[1] = dup2(a0.y); ad[2] = dup2(a0.z); ad[3] = dup2(a0.w);
            ad[4] = dup2(a1.x); ad[5] = dup2(a1.y); ad[6] = dup2(a1.z); ad[7] = dup2(a1.w);
#pragma unroll
            for (int i = 0; i < 8; i++) {
                fma2(acc[i][0], ad[i], b01.x);
                fma2(acc[i][1], ad[i], b01.y);
                fma2(acc[i][2], ad[i], b23.x);
                fma2(acc[i][3], ad[i], b23.y);
            }
        }
        __syncthreads();
    }

    float ubb[8];
#pragma unroll
    for (int j = 0; j < 8; j++) {
        int n = n0 + tx * 8 + j;
        ubb[j] = Ub[n] + bvec[n];
    }
#pragma unroll
    for (int i = 0; i < 8; i++) {
        float2 p0 = unpk(acc[i][0]);
        float2 p1 = unpk(acc[i][1]);
        float2 p2 = unpk(acc[i][2]);
        float2 p3 = unpk(acc[i][3]);
        float* dst = out + (size_t)(m0 + ty * 8 + i) * H_ + n0 + tx * 8;
        float4 v0 = make_float4(p0.x + ubb[0], p0.y + ubb[1],
                                p1.x + ubb[2], p1.y + ubb[3]);
        float4 v1 = make_float4(p2.x + ubb[4], p2.y + ubb[5],
                                p3.x + ubb[6], p3.y + ubb[7]);
        *(float4*)dst       = v0;
        *(float4*)(dst + 4) = v1;
    }
}

// ---------------------------------------------------------------------------
// Persistent fp32 recurrence (FFMA2) — R12 numerics & barrier, but 512 threads
// (2x warps -> latency hiding). Per-thread tile 2(b) x 4(n), same k order per
// output => bit-identical accumulation to R12.
//   out[b][t][n] += sum_k out[b][t-1][k] * Uw[n][k]
// ---------------------------------------------------------------------------
__global__ __launch_bounds__(512) void rnn_persistent_kernel(float* __restrict__ out)
{
    __shared__ float Ss[64][132];    // [b][k-slab], padded
    __shared__ float Us[128][64];    // [k-slab][n-tile]
    const int tid = threadIdx.x;
    const int bid = blockIdx.x;
    const int n0 = (bid & 15) * 64;
    const int k0 = (bid >> 4) * 128;
    const int ty = tid >> 4;         // 0..31 -> b-pair
    const int tx = tid & 15;         // 0..15 -> n-quad

    // Preload UwT slab (128 x 64 floats) once.
#pragma unroll
    for (int l = 0; l < 4; l++) {
        int idx = tid + l * 512;     // 0..2047
        int r  = idx >> 4;           // 0..127 (k)
        int c4 = (idx & 15) << 2;    // 0..60  (n)
        *(float4*)&Us[r][c4] =
            *(const float4*)(g_UwT + (size_t)(k0 + r) * H_ + n0 + c4);
    }
    __syncthreads();

    for (int t = 1; t < T_; t++) {
        const float* prev = out + (size_t)(t - 1) * H_ + k0;
#pragma unroll
        for (int l = 0; l < 4; l++) {
            int idx = tid + l * 512;   // 0..2047
            int b   = idx >> 5;        // 0..63
            int c4  = (idx & 31) << 2; // 0..124
            *(float4*)&Ss[b][c4] =
                *(const float4*)(prev + (size_t)b * BSTRIDE + c4);
        }
        __syncthreads();

        unsigned long long acc[2][2];   // 2 b-rows x 2 n-pairs (4 n-cols)
        acc[0][0] = 0ull; acc[0][1] = 0ull;
        acc[1][0] = 0ull; acc[1][1] = 0ull;

#pragma unroll 8
        for (int k = 0; k < 128; k += 2) {
            ulonglong2 bb0 = *(const ulonglong2*)&Us[k][tx * 4];     // k:   n-pairs
            ulonglong2 bb1 = *(const ulonglong2*)&Us[k + 1][tx * 4]; // k+1: n-pairs
            float2 a0 = *(const float2*)&Ss[ty * 2 + 0][k];
            float2 a1 = *(const float2*)&Ss[ty * 2 + 1][k];
            // k term, then k+1 term — same per-output order as R12
            unsigned long long d;
            d = dup2(a0.x); fma2(acc[0][0], d, bb0.x); fma2(acc[0][1], d, bb0.y);
            d = dup2(a0.y); fma2(acc[0][0], d, bb1.x); fma2(acc[0][1], d, bb1.y);
            d = dup2(a1.x); fma2(acc[1][0], d, bb0.x); fma2(acc[1][1], d, bb0.y);
            d = dup2(a1.y); fma2(acc[1][0], d, bb1.x); fma2(acc[1][1], d, bb1.y);
        }

#pragma unroll
        for (int i = 0; i < 2; i++) {
            float2 p0 = unpk(acc[i][0]);
            float2 p1 = unpk(acc[i][1]);
            float* dst = out + (size_t)(ty * 2 + i) * BSTRIDE
                             + (size_t)t * H_ + n0 + tx * 4;
            asm volatile("red.global.add.v4.f32 [%0], {%1,%2,%3,%4};"
                         :: "l"(dst), "f"(p0.x), "f"(p0.y), "f"(p1.x), "f"(p1.y)
                         : "memory");
        }

        // R12-validated lockstep barrier
        if (t < T_ - 1) {
            __threadfence();
            __syncthreads();   // join ALL warps' REDs before tid0 arrives
            if (tid == 0) {
                unsigned target = (unsigned)t * NBLK;
                atomicAdd(&g_bar, 1u);
                unsigned v;
                do {
                    asm volatile("ld.acquire.gpu.global.u32 %0, [%1];"
                                 : "=r"(v) : "l"(&g_bar));
                } while (v < target);
            }
            __syncthreads();
        }
    }
}

// ---------------------------------------------------------------------------
extern "C" void kernel_launch(void* const* d_in, const int* in_sizes, int n_in,
                              void* d_out, int out_size) {
    (void)in_sizes; (void)n_in; (void)out_size;
    const float* x   = (const float*)d_in[0];
    const float* W   = (const float*)d_in[1];
    const float* Uw  = (const float*)d_in[2];
    const float* Ub  = (const float*)d_in[3];
    const float* bv  = (const float*)d_in[4];
    float* out = (float*)d_out;

    // 1) transpose Uw -> g_UwT and reset barrier counter
    uw_transpose_kernel<<<dim3(H_ / 32, H_ / 32), 256>>>(Uw);

    // 2) wx = x @ W^T + Ub + b   (fp32 FFMA2)
    proj_kernel<<<dim3(H_ / 128, MTOT / 128), 256>>>(x, W, Ub, bv, out);

    // 3) all 2047 recurrence steps, fp32 FFMA2, 512 threads/block
    rnn_persistent_kernel<<<NBLK, 512>>>(out);
}

// round 15
// speedup vs baseline: 1.0610x; 1.0610x over previous
#include <cuda_runtime.h>
#include <cstdint>

#define B_ 64
#define T_ 2048
#define I_ 512
#define H_ 1024
#define MTOT (B_ * T_)
#define BSTRIDE ((size_t)T_ * H_)   // stride between batch rows in out
#define NBLK 128                    // persistent grid: 8 n-tiles x 16 k-slabs
#define SSTR 68                     // Ss row stride ([k][b], +4 pad)

// Scratch: Uw transposed to [k][n] (R4-validated).
__device__ float g_UwT[H_ * H_];
__device__ unsigned g_bar;          // grid-barrier arrival counter

// ---------------------------------------------------------------------------
// packed-fp32 helpers (FFMA2 via PTX fma.rn.f32x2; exact IEEE RN per lane)
// ---------------------------------------------------------------------------
__device__ __forceinline__ unsigned long long dup2(float x) {
    unsigned long long r; unsigned u = __float_as_uint(x);
    asm("mov.b64 %0, {%1, %2};" : "=l"(r) : "r"(u), "r"(u));
    return r;
}
__device__ __forceinline__ void fma2(unsigned long long& d,
                                     unsigned long long a, unsigned long long b) {
    asm("fma.rn.f32x2 %0, %1, %2, %0;" : "+l"(d) : "l"(a), "l"(b));
}
__device__ __forceinline__ float2 unpk(unsigned long long v) {
    unsigned lo, hi;
    asm("mov.b64 {%0, %1}, %2;" : "=r"(lo), "=r"(hi) : "l"(v));
    return make_float2(__uint_as_float(lo), __uint_as_float(hi));
}

// ---------------------------------------------------------------------------
// Transpose Uw[n][k] -> g_UwT[k][n]; also reset the grid barrier. (R4-validated)
// ---------------------------------------------------------------------------
__global__ __launch_bounds__(256) void uw_transpose_kernel(const float* __restrict__ Uw) {
    if (blockIdx.x == 0 && blockIdx.y == 0 && threadIdx.x == 0) g_bar = 0u;
    __shared__ float tile[32][33];
    const int bx = blockIdx.x * 32;
    const int by = blockIdx.y * 32;
    const int tx = threadIdx.x & 31;
    const int tw = threadIdx.x >> 5;
#pragma unroll
    for (int r = 0; r < 32; r += 8)
        tile[tw + r][tx] = Uw[(size_t)(by + tw + r) * H_ + bx + tx];
    __syncthreads();
#pragma unroll
    for (int r = 0; r < 32; r += 8)
        g_UwT[(size_t)(bx + tw + r) * H_ + by + tx] = tile[tx][tw + r];
}

// ---------------------------------------------------------------------------
// Projection (fp32 FFMA2) — R12-validated. out = x@W^T + Ub + b.
// ---------------------------------------------------------------------------
__global__ __launch_bounds__(256) void proj_kernel(
    const float* __restrict__ x, const float* __restrict__ W,
    const float* __restrict__ Ub, const float* __restrict__ bvec,
    float* __restrict__ out)
{
    __shared__ float As[16][128];
    __shared__ float Bs[16][128];
    const int tid = threadIdx.x;
    const int m0 = blockIdx.y * 128;
    const int n0 = blockIdx.x * 128;
    const int ty = tid >> 4;   // 0..15
    const int tx = tid & 15;   // 0..15

    unsigned long long acc[8][4];
#pragma unroll
    for (int i = 0; i < 8; i++)
#pragma unroll
        for (int j = 0; j < 4; j++) acc[i][j] = 0ull;

    for (int kb = 0; kb < I_; kb += 16) {
#pragma unroll
        for (int l = 0; l < 2; l++) {
            int idx = tid + l * 256;
            int row = idx >> 2;
            int c4  = (idx & 3) << 2;
            float4 av = *(const float4*)(x + (size_t)(m0 + row) * I_ + kb + c4);
            As[c4 + 0][row] = av.x; As[c4 + 1][row] = av.y;
            As[c4 + 2][row] = av.z; As[c4 + 3][row] = av.w;
            float4 wv = *(const float4*)(W + (size_t)(n0 + row) * I_ + kb + c4);
            Bs[c4 + 0][row] = wv.x; Bs[c4 + 1][row] = wv.y;
            Bs[c4 + 2][row] = wv.z; Bs[c4 + 3][row] = wv.w;
        }
        __syncthreads();
#pragma unroll
        for (int k = 0; k < 16; k++) {
            float4 a0 = *(const float4*)&As[k][ty * 8];
            float4 a1 = *(const float4*)&As[k][ty * 8 + 4];
            ulonglong2 b01 = *(const ulonglong2*)&Bs[k][tx * 8];
            ulonglong2 b23 = *(const ulonglong2*)&Bs[k][tx * 8 + 4];
            unsigned long long ad[8];
            ad[0] = dup2(a0.x); ad[1] = dup2(a0.y); ad[2] = dup2(a0.z); ad[3] = dup2(a0.w);
            ad[4] = dup2(a1.x); ad[5] = dup2(a1.y); ad[6] = dup2(a1.z); ad[7] = dup2(a1.w);
#pragma unroll
            for (int i = 0; i < 8; i++) {
                fma2(acc[i][0], ad[i], b01.x);
                fma2(acc[i][1], ad[i], b01.y);
                fma2(acc[i][2], ad[i], b23.x);
                fma2(acc[i][3], ad[i], b23.y);
            }
        }
        __syncthreads();
    }

    float ubb[8];
#pragma unroll
    for (int j = 0; j < 8; j++) {
        int n = n0 + tx * 8 + j;
        ubb[j] = Ub[n] + bvec[n];
    }
#pragma unroll
    for (int i = 0; i < 8; i++) {
        float2 p0 = unpk(acc[i][0]);
        float2 p1 = unpk(acc[i][1]);
        float2 p2 = unpk(acc[i][2]);
        float2 p3 = unpk(acc[i][3]);
        float* dst = out + (size_t)(m0 + ty * 8 + i) * H_ + n0 + tx * 8;
        float4 v0 = make_float4(p0.x + ubb[0], p0.y + ubb[1],
                                p1.x + ubb[2], p1.y + ubb[3]);
        float4 v1 = make_float4(p2.x + ubb[4], p2.y + ubb[5],
                                p3.x + ubb[6], p3.y + ubb[7]);
        *(float4*)dst       = v0;
        *(float4*)(dst + 4) = v1;
    }
}

// ---------------------------------------------------------------------------
// Persistent fp32 recurrence (FFMA2), LDS-minimized layout:
//   grid: (bid & 7) -> n-tile of 128 cols; (bid >> 3) -> k-slab of 64.
//   256 threads, thread tile 4(b) x 8(n); ty = tid&15 (b varies in half-warp)
//   => B loads broadcast (1 wf), A loads one conflict-free LDS.128 (2 wf).
//   Per-step smem traffic ~2048 wf (half the 4096-cyc FFMA2 floor).
//   out[b][t][n] += sum_k out[b][t-1][k] * Uw[n][k]
// R12 numerics (k ascending per output) and R12 lockstep barrier.
// ---------------------------------------------------------------------------
__global__ __launch_bounds__(256) void rnn_persistent_kernel(float* __restrict__ out)
{
    extern __shared__ float sm[];
    float* Us = sm;                 // [64 k][128 n], stride 128
    float* Ss = sm + 64 * 128;      // [64 k][64 b], stride SSTR=68

    const int tid = threadIdx.x;
    const int bid = blockIdx.x;
    const int n0 = (bid & 7) * 128;
    const int k0 = (bid >> 3) * 64;
    const int ty = tid & 15;        // b-quad   (varies within half-warp)
    const int tx = tid >> 4;        // n-oct    (constant within half-warp)

    // Preload Uw slab [64 k][128 n] once (float4, conflict-free).
#pragma unroll
    for (int l = 0; l < 8; l++) {
        int idx = tid + l * 256;    // 0..2047
        int r  = idx >> 5;          // 0..63  (k)
        int c4 = (idx & 31) << 2;   // 0..124 (n)
        *(float4*)&Us[r * 128 + c4] =
            *(const float4*)(g_UwT + (size_t)(k0 + r) * H_ + n0 + c4);
    }
    __syncthreads();

    for (int t = 1; t < T_; t++) {
        // Stage prev state [64 b][64 k] -> Ss[k][b] (coalesced LDG, STS transpose)
        const float* prev = out + (size_t)(t - 1) * H_ + k0;
#pragma unroll
        for (int l = 0; l < 4; l++) {
            int idx = tid + l * 256;   // 0..1023
            int b   = idx >> 4;        // 0..63
            int c4  = (idx & 15) << 2; // 0..60 (k)
            float4 v = *(const float4*)(prev + (size_t)b * BSTRIDE + c4);
            Ss[(c4 + 0) * SSTR + b] = v.x;
            Ss[(c4 + 1) * SSTR + b] = v.y;
            Ss[(c4 + 2) * SSTR + b] = v.z;
            Ss[(c4 + 3) * SSTR + b] = v.w;
        }
        __syncthreads();

        unsigned long long acc[4][4];   // 4 b-rows x 4 n-pairs (8 n-cols)
#pragma unroll
        for (int i = 0; i < 4; i++)
#pragma unroll
            for (int j = 0; j < 4; j++) acc[i][j] = 0ull;

#pragma unroll 8
        for (int k = 0; k < 64; k++) {
            float4 a = *(const float4*)&Ss[k * SSTR + ty * 4];          // 4 b at k
            ulonglong2 u01 = *(const ulonglong2*)&Us[k * 128 + tx * 8];     // n+0..3
            ulonglong2 u23 = *(const ulonglong2*)&Us[k * 128 + tx * 8 + 4]; // n+4..7
            unsigned long long d;
            d = dup2(a.x);
            fma2(acc[0][0], d, u01.x); fma2(acc[0][1], d, u01.y);
            fma2(acc[0][2], d, u23.x); fma2(acc[0][3], d, u23.y);
            d = dup2(a.y);
            fma2(acc[1][0], d, u01.x); fma2(acc[1][1], d, u01.y);
            fma2(acc[1][2], d, u23.x); fma2(acc[1][3], d, u23.y);
            d = dup2(a.z);
            fma2(acc[2][0], d, u01.x); fma2(acc[2][1], d, u01.y);
            fma2(acc[2][2], d, u23.x); fma2(acc[2][3], d, u23.y);
            d = dup2(a.w);
            fma2(acc[3][0], d, u01.x); fma2(acc[3][1], d, u01.y);
            fma2(acc[3][2], d, u23.x); fma2(acc[3][3], d, u23.y);
        }

        // Merge partials onto wx at out[:, t, :] (2 red.v4 per b-row)
#pragma unroll
        for (int i = 0; i < 4; i++) {
            float2 p0 = unpk(acc[i][0]);
            float2 p1 = unpk(acc[i][1]);
            float2 p2 = unpk(acc[i][2]);
            float2 p3 = unpk(acc[i][3]);
            float* dst = out + (size_t)(ty * 4 + i) * BSTRIDE
                             + (size_t)t * H_ + n0 + tx * 8;
            asm volatile("red.global.add.v4.f32 [%0], {%1,%2,%3,%4};"
                         :: "l"(dst), "f"(p0.x), "f"(p0.y), "f"(p1.x), "f"(p1.y)
                         : "memory");
            asm volatile("red.global.add.v4.f32 [%0], {%1,%2,%3,%4};"
                         :: "l"(dst + 4), "f"(p2.x), "f"(p2.y), "f"(p3.x), "f"(p3.y)
                         : "memory");
        }

        // R12-validated lockstep barrier
        if (t < T_ - 1) {
            __threadfence();
            __syncthreads();   // join ALL warps' REDs before tid0 arrives
            if (tid == 0) {
                unsigned target = (unsigned)t * NBLK;
                atomicAdd(&g_bar, 1u);
                unsigned v;
                do {
                    asm volatile("ld.acquire.gpu.global.u32 %0, [%1];"
                                 : "=r"(v) : "l"(&g_bar));
                } while (v < target);
            }
            __syncthreads();
        }
    }
}

// ---------------------------------------------------------------------------
extern "C" void kernel_launch(void* const* d_in, const int* in_sizes, int n_in,
                              void* d_out, int out_size) {
    (void)in_sizes; (void)n_in; (void)out_size;
    const float* x   = (const float*)d_in[0];
    const float* W   = (const float*)d_in[1];
    const float* Uw  = (const float*)d_in[2];
    const float* Ub  = (const float*)d_in[3];
    const float* bv  = (const float*)d_in[4];
    float* out = (float*)d_out;

    const int rnn_smem = (64 * 128 + 64 * SSTR) * 4;   // 32768 + 17408 = 50176 B
    cudaFuncSetAttribute(rnn_persistent_kernel,
                         cudaFuncAttributeMaxDynamicSharedMemorySize, rnn_smem);

    // 1) transpose Uw -> g_UwT and reset barrier counter
    uw_transpose_kernel<<<dim3(H_ / 32, H_ / 32), 256>>>(Uw);

    // 2) wx = x @ W^T + Ub + b   (fp32 FFMA2)
    proj_kernel<<<dim3(H_ / 128, MTOT / 128), 256>>>(x, W, Ub, bv, out);

    // 3) all 2047 recurrence steps, LDS-minimized FFMA2 persistent kernel
    rnn_persistent_kernel<<<NBLK, 256, rnn_smem>>>(out);
}